// round 10
// baseline (speedup 1.0000x reference)
#include <cuda_runtime.h>
#include <math.h>

// RRoIAlign:
//   K1: NCHW (8,32,160,160) -> NHWC scratch (8,160,160,32). XOR-swizzled float4
//       tile: LDG.128 + STS.128 CF in, scalar LDS CF out + STG.128 coalesced.
//   K2: grid (1024 rois, 4 row-pairs) x 512 threads; geometry by 128 threads into
//       smem; per-row float4 tap gathers (coalesced, 4 bins/warp); stride-65
//       staging (CF STS); epilogue remapped so LDS.32 x4 is conflict-free
//       (warp = 4 c x 8 x4) while STG.128 stays coalesced.

namespace {

constexpr int PH = 8;
constexpr int PW = 64;
constexpr int CC = 32;
constexpr int HH = 160;
constexpr int WW = 160;
constexpr int BB = 8;
constexpr float SCALE = 0.25f;

constexpr int IMG   = HH * WW * CC;          // 819200 floats per image
constexpr int ROWF  = WW * CC;               // 5120 floats per pixel-row
constexpr int GUARD = 524288;                // 2MB zero guard each side

__device__ float g_nhwc[GUARD + (size_t)BB * IMG + GUARD];

// ---------------- K1: NCHW -> NHWC transpose (XOR-swizzled tile) ----------------
__global__ __launch_bounds__(256) void transpose_kernel(const float* __restrict__ feat)
{
    __shared__ float4 tile[CC * 40];         // [c][sxq], sxq = xq ^ ((c>>2)&7)
    const int b = blockIdx.x / HH;
    const int y = blockIdx.x - b * HH;

    // phase 1: coalesced LDG.128, conflict-free STS.128
    const float4* src = reinterpret_cast<const float4*>(feat + (size_t)b * IMG + (size_t)y * WW);
#pragma unroll
    for (int f = threadIdx.x; f < CC * 40; f += 256) {       // 5 iters
        const int c  = f / 40;
        const int xq = f - c * 40;
        const int sxq = xq ^ ((c >> 2) & 7);
        tile[c * 40 + sxq] = __ldg(src + (size_t)c * (HH * WW / 4) + xq);
    }
    __syncthreads();

    // phase 2: 4 scalar LDS (CF: bank = 4*((xq%8)^cg) + xr) + STG.128 coalesced
    const float* tf = reinterpret_cast<const float*>(tile);
    float* dst = g_nhwc + GUARD + (size_t)b * IMG + (size_t)y * ROWF;
#pragma unroll
    for (int g = threadIdx.x; g < (WW * CC) / 4; g += 256) { // 5 iters
        const int x  = g >> 3;
        const int cg = g & 7;
        const int xq = x >> 2;
        const int xr = x & 3;
        const int sxq = xq ^ cg;             // ((4cg+j)>>2)&7 == cg for j<4
        float4 v;
        v.x = tf[((4 * cg + 0) * 40 + sxq) * 4 + xr];
        v.y = tf[((4 * cg + 1) * 40 + sxq) * 4 + xr];
        v.z = tf[((4 * cg + 2) * 40 + sxq) * 4 + xr];
        v.w = tf[((4 * cg + 3) * 40 + sxq) * 4 + xr];
        *reinterpret_cast<float4*>(dst + (size_t)x * CC + 4 * cg) = v;
    }
}

// ---------------- K2: gather + blend, 2 rows per block ----------------
__global__ __launch_bounds__(512) void rroi_gather_kernel(
    const float* __restrict__ rois,
    float* __restrict__ out)
{
    __shared__ int    s_base[2 * PW];         // slot = row_local*64 + pw
    __shared__ float4 s_wv[2 * PW];
    __shared__ float  s_r[2][CC * 65];        // staging, odd stride (CF STS)

    const int n   = blockIdx.x;
    const int tid = threadIdx.x;

    if (tid < 2 * PW) {
        const float2* rp = reinterpret_cast<const float2*>(rois + (size_t)n * 6);
        const float2 ra = __ldg(rp + 0);   // batch_idx, cx
        const float2 rb = __ldg(rp + 1);   // cy, h
        const float2 rc = __ldg(rp + 2);   // w, ang

        const int   bidx = (int)ra.x;
        const float cx = ra.y, cy = rb.x, hh = rb.y, ww = rc.x, ang = rc.y;

        const float theta = ang * 0.017453292519943295f;
        float sa, ca;
        sincosf(theta, &sa, &ca);

        const float Sx = ww * SCALE / (float)PW;
        const float Sy = hh * SCALE / (float)PH;
        const float dxc = -(float)PW * 0.5f;
        const float dyc = -(float)PH * 0.5f;
        const float Dx = cx * SCALE;
        const float Dy = cy * SCALE;

        const float M00 = ca * Sx;
        const float M01 = sa * Sy;
        const float M02 = M00 * dxc + M01 * dyc + Dx;
        const float M10 = -sa * Sx;
        const float M11 = ca * Sy;
        const float M12 = M10 * dxc + M11 * dyc + Dy;

        const float pw  = (float)(tid & (PW - 1));
        const float ph  = (float)(blockIdx.y * 2 + (tid >> 6));
        const float pw1 = pw + 1.0f;
        const float ph1 = ph + 1.0f;

        const float X0 = M00 * pw  + M01 * ph  + M02;
        const float X1 = M00 * pw  + M01 * ph1 + M02;
        const float X2 = M00 * pw1 + M01 * ph  + M02;
        const float X3 = M00 * pw1 + M01 * ph1 + M02;
        const float Y0 = M10 * pw  + M11 * ph  + M12;
        const float Y1 = M10 * pw  + M11 * ph1 + M12;
        const float Y2 = M10 * pw1 + M11 * ph  + M12;
        const float Y3 = M10 * pw1 + M11 * ph1 + M12;

        const float xmn = fminf(fminf(X0, X1), fminf(X2, X3));
        const float xmx = fmaxf(fmaxf(X0, X1), fmaxf(X2, X3));
        const float ymn = fminf(fminf(Y0, Y1), fminf(Y2, Y3));
        const float ymx = fmaxf(fmaxf(Y0, Y1), fmaxf(Y2, Y3));

        const float left   = fmaxf(floorf(xmn + 0.5f), 0.0f);
        const float right  = fminf(floorf(xmx + 0.5f), (float)(WW - 1));
        const float top    = fmaxf(floorf(ymn + 0.5f), 0.0f);
        const float bottom = fminf(floorf(ymx + 0.5f), (float)(HH - 1));

        const float bcx = (left + right) * 0.5f;
        const float bcy = (top + bottom) * 0.5f;

        const float bl = floorf(bcx);
        const float br = ceilf(bcx);
        const float bt = floorf(bcy);
        const float bb = ceilf(bcy);
        const float rx = bcx - bl;
        const float ry = bcy - bt;

        const bool vl = (bl > -1.0f) && (bl < (float)WW);
        const bool vr = (br > -1.0f) && (br < (float)WW);
        const bool vt = (bt > -1.0f) && (bt < (float)HH);
        const bool vb = (bb > -1.0f) && (bb < (float)HH);

        // nonzero weight implies ceil==floor+1 on that axis, so the fixed 2x2
        // patch at (yt..yt+1, xl..xl+1) is exact; zero-weight taps may touch
        // the zeroed guard band harmlessly.
        float wlt = (1.0f - rx) * (1.0f - ry);
        float wrt = rx * (1.0f - ry);
        float wlb = (1.0f - rx) * ry;
        float wrb = rx * ry;
        if (!(vt && vl)) wlt = 0.0f;
        if (!(vt && vr)) wrt = 0.0f;
        if (!(vb && vl)) wlb = 0.0f;
        if (!(vb && vr)) wrb = 0.0f;

        const int xl = (int)bl;
        const int yt = (int)bt;

        s_base[tid] = bidx * IMG + (yt * WW + xl) * CC;
        s_wv[tid]   = make_float4(wlt, wrt, wlb, wrb);
    }
    __syncthreads();

    const int bin = tid >> 3;            // 0..63
    const int cg  = tid & 7;             // 4-channel group
    const float* g = g_nhwc + GUARD;

#pragma unroll
    for (int rl = 0; rl < 2; rl++) {
        const int slot  = rl * PW + bin;
        const int base  = s_base[slot] + cg * 4;
        const float4 w  = s_wv[slot];

        const float4 t00 = *reinterpret_cast<const float4*>(g + base);
        const float4 t01 = *reinterpret_cast<const float4*>(g + base + CC);
        const float4 t10 = *reinterpret_cast<const float4*>(g + base + ROWF);
        const float4 t11 = *reinterpret_cast<const float4*>(g + base + ROWF + CC);

        float4 v;
        v.x = w.x * t00.x + w.y * t01.x + w.z * t10.x + w.w * t11.x;
        v.y = w.x * t00.y + w.y * t01.y + w.z * t10.y + w.w * t11.y;
        v.z = w.x * t00.z + w.y * t01.z + w.z * t10.z + w.w * t11.z;
        v.w = w.x * t00.w + w.y * t01.w + w.z * t10.w + w.w * t11.w;

        const int c0 = cg * 4;
        s_r[rl][(c0 + 0) * 65 + bin] = v.x;   // odd stride: conflict-free STS
        s_r[rl][(c0 + 1) * 65 + bin] = v.y;
        s_r[rl][(c0 + 2) * 65 + bin] = v.z;
        s_r[rl][(c0 + 3) * 65 + bin] = v.w;
    }
    __syncthreads();

    // epilogue: warp = 4 c-values x 8 x4-values
    //   LDS banks: c_base + (lane>>3) + 4*(lane&7) + j -> all 32 distinct (CF)
    //   STG.128: per c a contiguous 128B run -> fully coalesced
    const int w_id = tid >> 5;
    const int lane = tid & 31;
    const int c  = ((w_id & 7) << 2) + (lane >> 3);   // 0..31
    const int x4 = ((w_id >> 3) << 3) + (lane & 7);   // 0..15
    const int r0 = blockIdx.y * 2;
    float* ob = out + (size_t)n * (CC * PH * PW) + (size_t)c * (PH * PW);

#pragma unroll
    for (int rl = 0; rl < 2; rl++) {
        const float* sr = &s_r[rl][c * 65 + x4 * 4];
        float4 v;
        v.x = sr[0];
        v.y = sr[1];
        v.z = sr[2];
        v.w = sr[3];
        *reinterpret_cast<float4*>(ob + (r0 + rl) * PW + x4 * 4) = v;
    }
}

}  // namespace

extern "C" void kernel_launch(void* const* d_in, const int* in_sizes, int n_in,
                              void* d_out, int out_size) {
    const float* features = (const float*)d_in[0];
    const float* rois     = (const float*)d_in[1];
    float* out            = (float*)d_out;

    const int N = in_sizes[1] / 6;  // 1024

    transpose_kernel<<<BB * HH, 256>>>(features);
    dim3 grid(N, PH / 2);
    rroi_gather_kernel<<<grid, 512>>>(rois, out);
}

// round 11
// speedup vs baseline: 1.2049x; 1.2049x over previous
#include <cuda_runtime.h>
#include <cuda_fp16.h>
#include <math.h>

// RRoIAlign:
//   K1: NCHW (8,32,160,160) f32 -> NHWC fp16 scratch (8,160,160,32). XOR-swizzled
//       f32 tile in smem; convert to fp16 at the coalesced STG.64.
//   K2: grid (1024 rois, 4 row-pairs) x 512 threads; geometry by 128 threads into
//       smem; per-row LDG.64 fp16 tap gathers (coalesced) -> fp32 blend; stride-65
//       staging (CF STS); CF epilogue LDS + coalesced STG.128 (fp32 out).

namespace {

constexpr int PH = 8;
constexpr int PW = 64;
constexpr int CC = 32;
constexpr int HH = 160;
constexpr int WW = 160;
constexpr int BB = 8;
constexpr float SCALE = 0.25f;

constexpr int IMG   = HH * WW * CC;          // 819200 elems per image
constexpr int ROWF  = WW * CC;               // 5120 elems per pixel-row
constexpr int GUARD = 524288;                // 1MB (half) zero guard each side

__device__ __half g_nhwc[GUARD + (size_t)BB * IMG + GUARD];

__device__ __forceinline__ float4 ld4h(const __half* p) {
    const uint2 u = *reinterpret_cast<const uint2*>(p);
    const float2 a = __half22float2(*reinterpret_cast<const __half2*>(&u.x));
    const float2 b = __half22float2(*reinterpret_cast<const __half2*>(&u.y));
    return make_float4(a.x, a.y, b.x, b.y);
}

// ---------------- K1: NCHW f32 -> NHWC f16 transpose ----------------
__global__ __launch_bounds__(256) void transpose_kernel(const float* __restrict__ feat)
{
    __shared__ float4 tile[CC * 40];         // [c][sxq], sxq = xq ^ ((c>>2)&7)
    const int b = blockIdx.x / HH;
    const int y = blockIdx.x - b * HH;

    // phase 1: coalesced LDG.128, conflict-free STS.128
    const float4* src = reinterpret_cast<const float4*>(feat + (size_t)b * (HH * WW * CC) + (size_t)y * WW);
#pragma unroll
    for (int f = threadIdx.x; f < CC * 40; f += 256) {       // 5 iters
        const int c  = f / 40;
        const int xq = f - c * 40;
        const int sxq = xq ^ ((c >> 2) & 7);
        tile[c * 40 + sxq] = __ldg(src + (size_t)c * (HH * WW / 4) + xq);
    }
    __syncthreads();

    // phase 2: 4 scalar LDS (CF) -> f16 convert -> coalesced STG.64
    const float* tf = reinterpret_cast<const float*>(tile);
    __half* dst = g_nhwc + GUARD + (size_t)b * IMG + (size_t)y * ROWF;
#pragma unroll
    for (int g = threadIdx.x; g < (WW * CC) / 4; g += 256) { // 5 iters
        const int x  = g >> 3;
        const int cg = g & 7;
        const int xq = x >> 2;
        const int xr = x & 3;
        const int sxq = xq ^ cg;             // ((4cg+j)>>2)&7 == cg for j<4
        float4 v;
        v.x = tf[((4 * cg + 0) * 40 + sxq) * 4 + xr];
        v.y = tf[((4 * cg + 1) * 40 + sxq) * 4 + xr];
        v.z = tf[((4 * cg + 2) * 40 + sxq) * 4 + xr];
        v.w = tf[((4 * cg + 3) * 40 + sxq) * 4 + xr];
        const __half2 h0 = __floats2half2_rn(v.x, v.y);
        const __half2 h1 = __floats2half2_rn(v.z, v.w);
        uint2 u;
        u.x = *reinterpret_cast<const unsigned int*>(&h0);
        u.y = *reinterpret_cast<const unsigned int*>(&h1);
        *reinterpret_cast<uint2*>(dst + (size_t)x * CC + 4 * cg) = u;   // 8B, coalesced
    }
}

// ---------------- K2: gather + blend, 2 rows per block ----------------
__global__ __launch_bounds__(512) void rroi_gather_kernel(
    const float* __restrict__ rois,
    float* __restrict__ out)
{
    __shared__ int    s_base[2 * PW];         // slot = row_local*64 + pw
    __shared__ float4 s_wv[2 * PW];
    __shared__ float  s_r[2][CC * 65];        // staging, odd stride (CF STS)

    const int n   = blockIdx.x;
    const int tid = threadIdx.x;

    if (tid < 2 * PW) {
        const float2* rp = reinterpret_cast<const float2*>(rois + (size_t)n * 6);
        const float2 ra = __ldg(rp + 0);   // batch_idx, cx
        const float2 rb = __ldg(rp + 1);   // cy, h
        const float2 rc = __ldg(rp + 2);   // w, ang

        const int   bidx = (int)ra.x;
        const float cx = ra.y, cy = rb.x, hh = rb.y, ww = rc.x, ang = rc.y;

        const float theta = ang * 0.017453292519943295f;
        float sa, ca;
        sincosf(theta, &sa, &ca);

        const float Sx = ww * SCALE / (float)PW;
        const float Sy = hh * SCALE / (float)PH;
        const float dxc = -(float)PW * 0.5f;
        const float dyc = -(float)PH * 0.5f;
        const float Dx = cx * SCALE;
        const float Dy = cy * SCALE;

        const float M00 = ca * Sx;
        const float M01 = sa * Sy;
        const float M02 = M00 * dxc + M01 * dyc + Dx;
        const float M10 = -sa * Sx;
        const float M11 = ca * Sy;
        const float M12 = M10 * dxc + M11 * dyc + Dy;

        const float pw  = (float)(tid & (PW - 1));
        const float ph  = (float)(blockIdx.y * 2 + (tid >> 6));
        const float pw1 = pw + 1.0f;
        const float ph1 = ph + 1.0f;

        const float X0 = M00 * pw  + M01 * ph  + M02;
        const float X1 = M00 * pw  + M01 * ph1 + M02;
        const float X2 = M00 * pw1 + M01 * ph  + M02;
        const float X3 = M00 * pw1 + M01 * ph1 + M02;
        const float Y0 = M10 * pw  + M11 * ph  + M12;
        const float Y1 = M10 * pw  + M11 * ph1 + M12;
        const float Y2 = M10 * pw1 + M11 * ph  + M12;
        const float Y3 = M10 * pw1 + M11 * ph1 + M12;

        const float xmn = fminf(fminf(X0, X1), fminf(X2, X3));
        const float xmx = fmaxf(fmaxf(X0, X1), fmaxf(X2, X3));
        const float ymn = fminf(fminf(Y0, Y1), fminf(Y2, Y3));
        const float ymx = fmaxf(fmaxf(Y0, Y1), fmaxf(Y2, Y3));

        const float left   = fmaxf(floorf(xmn + 0.5f), 0.0f);
        const float right  = fminf(floorf(xmx + 0.5f), (float)(WW - 1));
        const float top    = fmaxf(floorf(ymn + 0.5f), 0.0f);
        const float bottom = fminf(floorf(ymx + 0.5f), (float)(HH - 1));

        const float bcx = (left + right) * 0.5f;
        const float bcy = (top + bottom) * 0.5f;

        const float bl = floorf(bcx);
        const float br = ceilf(bcx);
        const float bt = floorf(bcy);
        const float bb = ceilf(bcy);
        const float rx = bcx - bl;
        const float ry = bcy - bt;

        const bool vl = (bl > -1.0f) && (bl < (float)WW);
        const bool vr = (br > -1.0f) && (br < (float)WW);
        const bool vt = (bt > -1.0f) && (bt < (float)HH);
        const bool vb = (bb > -1.0f) && (bb < (float)HH);

        // nonzero weight implies ceil==floor+1 on that axis, so the fixed 2x2
        // patch at (yt..yt+1, xl..xl+1) is exact; zero-weight taps may touch
        // the zeroed guard band harmlessly.
        float wlt = (1.0f - rx) * (1.0f - ry);
        float wrt = rx * (1.0f - ry);
        float wlb = (1.0f - rx) * ry;
        float wrb = rx * ry;
        if (!(vt && vl)) wlt = 0.0f;
        if (!(vt && vr)) wrt = 0.0f;
        if (!(vb && vl)) wlb = 0.0f;
        if (!(vb && vr)) wrb = 0.0f;

        const int xl = (int)bl;
        const int yt = (int)bt;

        s_base[tid] = bidx * IMG + (yt * WW + xl) * CC;
        s_wv[tid]   = make_float4(wlt, wrt, wlb, wrb);
    }
    __syncthreads();

    const int bin = tid >> 3;            // 0..63
    const int cg  = tid & 7;             // 4-channel group
    const __half* g = g_nhwc + GUARD;

#pragma unroll
    for (int rl = 0; rl < 2; rl++) {
        const int slot  = rl * PW + bin;
        const int base  = s_base[slot] + cg * 4;
        const float4 w  = s_wv[slot];

        const float4 t00 = ld4h(g + base);
        const float4 t01 = ld4h(g + base + CC);
        const float4 t10 = ld4h(g + base + ROWF);
        const float4 t11 = ld4h(g + base + ROWF + CC);

        float4 v;
        v.x = w.x * t00.x + w.y * t01.x + w.z * t10.x + w.w * t11.x;
        v.y = w.x * t00.y + w.y * t01.y + w.z * t10.y + w.w * t11.y;
        v.z = w.x * t00.z + w.y * t01.z + w.z * t10.z + w.w * t11.z;
        v.w = w.x * t00.w + w.y * t01.w + w.z * t10.w + w.w * t11.w;

        const int c0 = cg * 4;
        s_r[rl][(c0 + 0) * 65 + bin] = v.x;   // odd stride: conflict-free STS
        s_r[rl][(c0 + 1) * 65 + bin] = v.y;
        s_r[rl][(c0 + 2) * 65 + bin] = v.z;
        s_r[rl][(c0 + 3) * 65 + bin] = v.w;
    }
    __syncthreads();

    // epilogue: warp = 4 c-values x 8 x4-values -> CF LDS + coalesced STG.128
    const int w_id = tid >> 5;
    const int lane = tid & 31;
    const int c  = ((w_id & 7) << 2) + (lane >> 3);   // 0..31
    const int x4 = ((w_id >> 3) << 3) + (lane & 7);   // 0..15
    const int r0 = blockIdx.y * 2;
    float* ob = out + (size_t)n * (CC * PH * PW) + (size_t)c * (PH * PW);

#pragma unroll
    for (int rl = 0; rl < 2; rl++) {
        const float* sr = &s_r[rl][c * 65 + x4 * 4];
        float4 v;
        v.x = sr[0];
        v.y = sr[1];
        v.z = sr[2];
        v.w = sr[3];
        *reinterpret_cast<float4*>(ob + (r0 + rl) * PW + x4 * 4) = v;
    }
}

}  // namespace

extern "C" void kernel_launch(void* const* d_in, const int* in_sizes, int n_in,
                              void* d_out, int out_size) {
    const float* features = (const float*)d_in[0];
    const float* rois     = (const float*)d_in[1];
    float* out            = (float*)d_out;

    const int N = in_sizes[1] / 6;  // 1024

    transpose_kernel<<<BB * HH, 256>>>(features);
    dim3 grid(N, PH / 2);
    rroi_gather_kernel<<<grid, 512>>>(rois, out);
}

// round 12
// speedup vs baseline: 1.2062x; 1.0010x over previous
#include <cuda_runtime.h>
#include <cuda_fp16.h>
#include <math.h>

// RRoIAlign:
//   K1: NCHW (8,32,160,160) f32 -> NHWC fp16 scratch (8,160,160,32). XOR-swizzled
//       f32 tile in smem; convert to fp16 at the coalesced STG.64.
//   K2: grid (1024 rois, 4 row-pairs) x 512 threads; geometry by 128 threads into
//       smem; each thread owns one (row,bin) x 8-channel group: 4 taps via
//       LDG.128 fp16 (16B) -> fp32 blend -> stride-65 staging (CF STS);
//       CF epilogue LDS + coalesced STG.128 (fp32 out). Single data pass.

namespace {

constexpr int PH = 8;
constexpr int PW = 64;
constexpr int CC = 32;
constexpr int HH = 160;
constexpr int WW = 160;
constexpr int BB = 8;
constexpr float SCALE = 0.25f;

constexpr int IMG   = HH * WW * CC;          // 819200 elems per image
constexpr int ROWF  = WW * CC;               // 5120 elems per pixel-row
constexpr int GUARD = 524288;                // zero guard each side

__device__ __half g_nhwc[GUARD + (size_t)BB * IMG + GUARD];

// ---------------- K1: NCHW f32 -> NHWC f16 transpose ----------------
__global__ __launch_bounds__(256) void transpose_kernel(const float* __restrict__ feat)
{
    __shared__ float4 tile[CC * 40];         // [c][sxq], sxq = xq ^ ((c>>2)&7)
    const int b = blockIdx.x / HH;
    const int y = blockIdx.x - b * HH;

    // phase 1: coalesced LDG.128, conflict-free STS.128
    const float4* src = reinterpret_cast<const float4*>(feat + (size_t)b * (HH * WW * CC) + (size_t)y * WW);
#pragma unroll
    for (int f = threadIdx.x; f < CC * 40; f += 256) {       // 5 iters
        const int c  = f / 40;
        const int xq = f - c * 40;
        const int sxq = xq ^ ((c >> 2) & 7);
        tile[c * 40 + sxq] = __ldg(src + (size_t)c * (HH * WW / 4) + xq);
    }
    __syncthreads();

    // phase 2: 4 scalar LDS (CF) -> f16 convert -> coalesced STG.64
    const float* tf = reinterpret_cast<const float*>(tile);
    __half* dst = g_nhwc + GUARD + (size_t)b * IMG + (size_t)y * ROWF;
#pragma unroll
    for (int g = threadIdx.x; g < (WW * CC) / 4; g += 256) { // 5 iters
        const int x  = g >> 3;
        const int cg = g & 7;
        const int xq = x >> 2;
        const int xr = x & 3;
        const int sxq = xq ^ cg;             // ((4cg+j)>>2)&7 == cg for j<4
        float4 v;
        v.x = tf[((4 * cg + 0) * 40 + sxq) * 4 + xr];
        v.y = tf[((4 * cg + 1) * 40 + sxq) * 4 + xr];
        v.z = tf[((4 * cg + 2) * 40 + sxq) * 4 + xr];
        v.w = tf[((4 * cg + 3) * 40 + sxq) * 4 + xr];
        const __half2 h0 = __floats2half2_rn(v.x, v.y);
        const __half2 h1 = __floats2half2_rn(v.z, v.w);
        uint2 u;
        u.x = *reinterpret_cast<const unsigned int*>(&h0);
        u.y = *reinterpret_cast<const unsigned int*>(&h1);
        *reinterpret_cast<uint2*>(dst + (size_t)x * CC + 4 * cg) = u;   // 8B, coalesced
    }
}

// convert 8 fp16 (uint4) -> 8 fp32 and FMA into acc with scalar weight
__device__ __forceinline__ void fma8h(float* acc, uint4 u, float w) {
    const __half2* h = reinterpret_cast<const __half2*>(&u);
#pragma unroll
    for (int j = 0; j < 4; j++) {
        const float2 f = __half22float2(h[j]);
        acc[2 * j + 0] += w * f.x;
        acc[2 * j + 1] += w * f.y;
    }
}

// ---------------- K2: gather + blend, 2 rows per block, single pass ----------------
__global__ __launch_bounds__(512) void rroi_gather_kernel(
    const float* __restrict__ rois,
    float* __restrict__ out)
{
    __shared__ int    s_base[2 * PW];         // slot = row_local*64 + pw
    __shared__ float4 s_wv[2 * PW];
    __shared__ float  s_r[2][CC * 65];        // staging, odd stride (CF STS)

    const int n   = blockIdx.x;
    const int tid = threadIdx.x;

    if (tid < 2 * PW) {
        const float2* rp = reinterpret_cast<const float2*>(rois + (size_t)n * 6);
        const float2 ra = __ldg(rp + 0);   // batch_idx, cx
        const float2 rb = __ldg(rp + 1);   // cy, h
        const float2 rc = __ldg(rp + 2);   // w, ang

        const int   bidx = (int)ra.x;
        const float cx = ra.y, cy = rb.x, hh = rb.y, ww = rc.x, ang = rc.y;

        const float theta = ang * 0.017453292519943295f;
        float sa, ca;
        sincosf(theta, &sa, &ca);

        const float Sx = ww * SCALE / (float)PW;
        const float Sy = hh * SCALE / (float)PH;
        const float dxc = -(float)PW * 0.5f;
        const float dyc = -(float)PH * 0.5f;
        const float Dx = cx * SCALE;
        const float Dy = cy * SCALE;

        const float M00 = ca * Sx;
        const float M01 = sa * Sy;
        const float M02 = M00 * dxc + M01 * dyc + Dx;
        const float M10 = -sa * Sx;
        const float M11 = ca * Sy;
        const float M12 = M10 * dxc + M11 * dyc + Dy;

        const float pw  = (float)(tid & (PW - 1));
        const float ph  = (float)(blockIdx.y * 2 + (tid >> 6));
        const float pw1 = pw + 1.0f;
        const float ph1 = ph + 1.0f;

        const float X0 = M00 * pw  + M01 * ph  + M02;
        const float X1 = M00 * pw  + M01 * ph1 + M02;
        const float X2 = M00 * pw1 + M01 * ph  + M02;
        const float X3 = M00 * pw1 + M01 * ph1 + M02;
        const float Y0 = M10 * pw  + M11 * ph  + M12;
        const float Y1 = M10 * pw  + M11 * ph1 + M12;
        const float Y2 = M10 * pw1 + M11 * ph  + M12;
        const float Y3 = M10 * pw1 + M11 * ph1 + M12;

        const float xmn = fminf(fminf(X0, X1), fminf(X2, X3));
        const float xmx = fmaxf(fmaxf(X0, X1), fmaxf(X2, X3));
        const float ymn = fminf(fminf(Y0, Y1), fminf(Y2, Y3));
        const float ymx = fmaxf(fmaxf(Y0, Y1), fmaxf(Y2, Y3));

        const float left   = fmaxf(floorf(xmn + 0.5f), 0.0f);
        const float right  = fminf(floorf(xmx + 0.5f), (float)(WW - 1));
        const float top    = fmaxf(floorf(ymn + 0.5f), 0.0f);
        const float bottom = fminf(floorf(ymx + 0.5f), (float)(HH - 1));

        const float bcx = (left + right) * 0.5f;
        const float bcy = (top + bottom) * 0.5f;

        const float bl = floorf(bcx);
        const float br = ceilf(bcx);
        const float bt = floorf(bcy);
        const float bb = ceilf(bcy);
        const float rx = bcx - bl;
        const float ry = bcy - bt;

        const bool vl = (bl > -1.0f) && (bl < (float)WW);
        const bool vr = (br > -1.0f) && (br < (float)WW);
        const bool vt = (bt > -1.0f) && (bt < (float)HH);
        const bool vb = (bb > -1.0f) && (bb < (float)HH);

        // nonzero weight implies ceil==floor+1 on that axis, so the fixed 2x2
        // patch at (yt..yt+1, xl..xl+1) is exact; zero-weight taps may touch
        // the zeroed guard band harmlessly.
        float wlt = (1.0f - rx) * (1.0f - ry);
        float wrt = rx * (1.0f - ry);
        float wlb = (1.0f - rx) * ry;
        float wrb = rx * ry;
        if (!(vt && vl)) wlt = 0.0f;
        if (!(vt && vr)) wrt = 0.0f;
        if (!(vb && vl)) wlb = 0.0f;
        if (!(vb && vr)) wrb = 0.0f;

        const int xl = (int)bl;
        const int yt = (int)bt;

        s_base[tid] = bidx * IMG + (yt * WW + xl) * CC;
        s_wv[tid]   = make_float4(wlt, wrt, wlb, wrb);
    }
    __syncthreads();

    // one thread = one (row,bin) x 8-channel group
    const int rb  = tid >> 2;            // 0..127: row_local*64 + bin
    const int cg  = tid & 3;             // 8-channel group
    const int rowl = rb >> 6;
    const int bin  = rb & 63;

    const __half* g = g_nhwc + GUARD;
    const int base = s_base[rb] + cg * 8;
    const float4 w = s_wv[rb];

    const uint4 u00 = *reinterpret_cast<const uint4*>(g + base);
    const uint4 u01 = *reinterpret_cast<const uint4*>(g + base + CC);
    const uint4 u10 = *reinterpret_cast<const uint4*>(g + base + ROWF);
    const uint4 u11 = *reinterpret_cast<const uint4*>(g + base + ROWF + CC);

    float acc[8] = {0, 0, 0, 0, 0, 0, 0, 0};
    fma8h(acc, u00, w.x);
    fma8h(acc, u01, w.y);
    fma8h(acc, u10, w.z);
    fma8h(acc, u11, w.w);

    const int c0 = cg * 8;
#pragma unroll
    for (int j = 0; j < 8; j++) {
        // bank = (c0+j) + bin mod 32: lanes (8b + a) all distinct -> CF
        s_r[rowl][(c0 + j) * 65 + bin] = acc[j];
    }
    __syncthreads();

    // epilogue: warp = 4 c-values x 8 x4-values -> CF LDS + coalesced STG.128
    const int w_id = tid >> 5;
    const int lane = tid & 31;
    const int c  = ((w_id & 7) << 2) + (lane >> 3);   // 0..31
    const int x4 = ((w_id >> 3) << 3) + (lane & 7);   // 0..15
    const int r0 = blockIdx.y * 2;
    float* ob = out + (size_t)n * (CC * PH * PW) + (size_t)c * (PH * PW);

#pragma unroll
    for (int rl = 0; rl < 2; rl++) {
        const float* sr = &s_r[rl][c * 65 + x4 * 4];
        float4 v;
        v.x = sr[0];
        v.y = sr[1];
        v.z = sr[2];
        v.w = sr[3];
        *reinterpret_cast<float4*>(ob + (r0 + rl) * PW + x4 * 4) = v;
    }
}

}  // namespace

extern "C" void kernel_launch(void* const* d_in, const int* in_sizes, int n_in,
                              void* d_out, int out_size) {
    const float* features = (const float*)d_in[0];
    const float* rois     = (const float*)d_in[1];
    float* out            = (float*)d_out;

    const int N = in_sizes[1] / 6;  // 1024

    transpose_kernel<<<BB * HH, 256>>>(features);
    dim3 grid(N, PH / 2);
    rroi_gather_kernel<<<grid, 512>>>(rois, out);
}